// round 1
// baseline (speedup 1.0000x reference)
#include <cuda_runtime.h>
#include <cstdint>

#define NN 50000
#define EE 500000
#define FIN 160
#define NG  128

#define CDIV(a,b) (((a)+(b)-1)/(b))

// ---------------- device scratch (no allocation allowed) ----------------
__device__ __align__(16) float g_w[EE];
__device__ __align__(16) float g_dinv[NN];
__device__ __align__(16) float g_T1[NN * FIN];
__device__ __align__(16) float g_T2[NN * FIN];
__device__ __align__(16) float g_H1[NN * 128];
__device__ __align__(16) float g_H2[NN * 64];
__device__ __align__(16) float g_H3[NN * 32];
__device__ __align__(16) float g_Wm1[3 * 160 * 128];
__device__ __align__(16) float g_Wm2[3 * 128 * 64];
__device__ __align__(16) float g_Wm3[3 * 64 * 32];
__device__ __align__(16) float g_pool[NG * 32];
__device__ __align__(16) float g_cnt[NG];

// ---------------- helpers ----------------
__device__ __forceinline__ void red_add_v4(float* addr, float4 v) {
    asm volatile("red.global.add.v4.f32 [%0], {%1,%2,%3,%4};"
                 :: "l"(addr), "f"(v.x), "f"(v.y), "f"(v.z), "f"(v.w)
                 : "memory");
}

__global__ void zero_kernel(float4* __restrict__ p, int n4) {
    int i = blockIdx.x * blockDim.x + threadIdx.x;
    if (i < n4) p[i] = make_float4(0.f, 0.f, 0.f, 0.f);
}

// ---------------- graph normalization ----------------
__global__ void deg_kernel(const int* __restrict__ src, const float* __restrict__ ea) {
    int e = blockIdx.x * blockDim.x + threadIdx.x;
    if (e < EE) atomicAdd(&g_dinv[src[e]], ea[e]);
}

__global__ void dinv_kernel() {
    int i = blockIdx.x * blockDim.x + threadIdx.x;
    if (i < NN) {
        float d = g_dinv[i];
        g_dinv[i] = (d > 0.f) ? rsqrtf(d) : 0.f;
    }
}

__global__ void w_kernel(const int* __restrict__ src, const int* __restrict__ dst,
                         const float* __restrict__ ea) {
    int e = blockIdx.x * blockDim.x + threadIdx.x;
    if (e < EE) g_w[e] = -g_dinv[src[e]] * ea[e] * g_dinv[dst[e]];
}

// ---------------- weight prep: Wm = [W0 - W2, W1, 2*W2] ----------------
__global__ void wprep_kernel(const float* __restrict__ W, float* __restrict__ Wm, int FFout) {
    int t = blockIdx.x * blockDim.x + threadIdx.x;
    if (t >= 3 * FFout) return;
    int k = t / FFout;
    int rel = t - k * FFout;
    float v = W[t];
    float out;
    if (k == 0)      out = v - W[2 * FFout + rel];
    else if (k == 1) out = v;
    else             out = 2.f * v;
    Wm[t] = out;
}

// ---------------- sparse propagate: out[dst] += w * X[src]  (feature dim F = 4*F4) ----
__global__ void propagate_kernel(const float* __restrict__ X, float* __restrict__ out,
                                 const int* __restrict__ src, const int* __restrict__ dst,
                                 int F4, int total) {
    int t = blockIdx.x * blockDim.x + threadIdx.x;
    if (t >= total) return;
    int e = t / F4;
    int c = t - e * F4;
    float we = g_w[e];
    int s = src[e];
    int d = dst[e];
    float4 v = ((const float4*)X)[(size_t)s * F4 + c];
    float4 r = make_float4(we * v.x, we * v.y, we * v.z, we * v.w);
    red_add_v4(out + ((size_t)d * F4 + c) * 4, r);
}

// ---------------- fused GEMM: C = relu([A0|A1|A2] (MxK,K=3F) @ B (KxBN) + bias) -------
template <int BN>
__global__ void gemm_relu_kernel(const float* __restrict__ A0,
                                 const float* __restrict__ A1,
                                 const float* __restrict__ A2,
                                 const float* __restrict__ B,
                                 const float* __restrict__ bias,
                                 float* __restrict__ C,
                                 int M, int F, int do_relu) {
    const int BM = 128, BK = 16, TM = 8;
    const int TN = BN / 16;
    __shared__ float As[BK][BM];
    __shared__ float Bs[BK][BN];

    int t  = threadIdx.x;        // 0..255
    int tx = t & 15;
    int ty = t >> 4;
    int m0 = blockIdx.x * BM;
    int K  = 3 * F;

    float acc[TM][TN];
#pragma unroll
    for (int i = 0; i < TM; ++i)
#pragma unroll
        for (int j = 0; j < TN; ++j) acc[i][j] = 0.f;

    for (int k0 = 0; k0 < K; k0 += BK) {
        int seg = k0 / F;                       // F % 16 == 0 => tile never crosses segment
        const float* A = (seg == 0) ? A0 : ((seg == 1) ? A1 : A2);
        int kc = k0 - seg * F;

        // load A tile (128x16): 512 float4, 2 per thread, stored transposed
#pragma unroll
        for (int l = 0; l < 2; ++l) {
            int idx = t + l * 256;
            int row = idx >> 2;
            int c4  = (idx & 3) * 4;
            float4 v = make_float4(0.f, 0.f, 0.f, 0.f);
            int m = m0 + row;
            if (m < M) v = *(const float4*)(A + (size_t)m * F + kc + c4);
            As[c4 + 0][row] = v.x;
            As[c4 + 1][row] = v.y;
            As[c4 + 2][row] = v.z;
            As[c4 + 3][row] = v.w;
        }
        // load B tile (16xBN)
        for (int idx = t; idx < BK * BN / 4; idx += 256) {
            int row = idx / (BN / 4);
            int c4  = (idx % (BN / 4)) * 4;
            float4 v = *(const float4*)(B + (size_t)(k0 + row) * BN + c4);
            *(float4*)&Bs[row][c4] = v;
        }
        __syncthreads();

#pragma unroll
        for (int kk = 0; kk < BK; ++kk) {
            float a[TM], b[TN];
#pragma unroll
            for (int i = 0; i < TM; ++i) a[i] = As[kk][ty + 16 * i];
#pragma unroll
            for (int j = 0; j < TN; ++j) b[j] = Bs[kk][tx + 16 * j];
#pragma unroll
            for (int i = 0; i < TM; ++i)
#pragma unroll
                for (int j = 0; j < TN; ++j) acc[i][j] = fmaf(a[i], b[j], acc[i][j]);
        }
        __syncthreads();
    }

#pragma unroll
    for (int i = 0; i < TM; ++i) {
        int m = m0 + ty + 16 * i;
        if (m >= M) continue;
#pragma unroll
        for (int j = 0; j < TN; ++j) {
            int col = tx + 16 * j;
            float v = acc[i][j] + bias[col];
            if (do_relu) v = fmaxf(v, 0.f);
            C[(size_t)m * BN + col] = v;
        }
    }
}

// ---------------- pooling + final linear ----------------
__global__ void pool_kernel(const int* __restrict__ batch) {
    int t = blockIdx.x * blockDim.x + threadIdx.x;
    if (t >= NN * 32) return;
    int i = t >> 5;
    int c = t & 31;
    int g = batch[i];
    atomicAdd(&g_pool[g * 32 + c], g_H3[t]);
    if (c == 0) atomicAdd(&g_cnt[g], 1.0f);
}

__global__ void final_kernel(const float* __restrict__ Wl, const float* __restrict__ bl,
                             float* __restrict__ out) {
    int t = threadIdx.x;
    if (t >= NG * 2) return;
    int g = t >> 1;
    int j = t & 1;
    float cnt = fmaxf(g_cnt[g], 1.0f);
    float s = 0.f;
#pragma unroll
    for (int c = 0; c < 32; ++c) s += g_pool[g * 32 + c] * Wl[c * 2 + j];
    out[t] = s / cnt + bl[j];
}

// ---------------- host orchestration ----------------
extern "C" void kernel_launch(void* const* d_in, const int* in_sizes, int n_in,
                              void* d_out, int out_size) {
    const float* x     = (const float*)d_in[0];
    const int*   ei    = (const int*)d_in[1];
    const float* ea    = (const float*)d_in[2];
    const int*   batch = (const int*)d_in[3];
    const float* W1    = (const float*)d_in[4];
    const float* b1    = (const float*)d_in[5];
    const float* W2    = (const float*)d_in[6];
    const float* b2    = (const float*)d_in[7];
    const float* W3    = (const float*)d_in[8];
    const float* b3    = (const float*)d_in[9];
    const float* Wl    = (const float*)d_in[10];
    const float* bl    = (const float*)d_in[11];
    const int* src = ei;
    const int* dst = ei + EE;

    float *pT1, *pT2, *pH1, *pH2, *pH3, *pWm1, *pWm2, *pWm3, *pdinv, *ppool, *pcnt;
    cudaGetSymbolAddress((void**)&pT1,  g_T1);
    cudaGetSymbolAddress((void**)&pT2,  g_T2);
    cudaGetSymbolAddress((void**)&pH1,  g_H1);
    cudaGetSymbolAddress((void**)&pH2,  g_H2);
    cudaGetSymbolAddress((void**)&pH3,  g_H3);
    cudaGetSymbolAddress((void**)&pWm1, g_Wm1);
    cudaGetSymbolAddress((void**)&pWm2, g_Wm2);
    cudaGetSymbolAddress((void**)&pWm3, g_Wm3);
    cudaGetSymbolAddress((void**)&pdinv, g_dinv);
    cudaGetSymbolAddress((void**)&ppool, g_pool);
    cudaGetSymbolAddress((void**)&pcnt,  g_cnt);

    const int T = 256;

    // normalization weights: deg -> dinv -> w
    zero_kernel<<<CDIV(NN / 4, T), T>>>((float4*)pdinv, NN / 4);
    deg_kernel<<<CDIV(EE, T), T>>>(src, ea);
    dinv_kernel<<<CDIV(NN, T), T>>>();
    w_kernel<<<CDIV(EE, T), T>>>(src, dst, ea);

    // modified weights per layer
    wprep_kernel<<<CDIV(3 * 160 * 128, T), T>>>(W1, pWm1, 160 * 128);
    wprep_kernel<<<CDIV(3 * 128 * 64, T), T>>>(W2, pWm2, 128 * 64);
    wprep_kernel<<<CDIV(3 * 64 * 32, T), T>>>(W3, pWm3, 64 * 32);

    // ---- layer 1: F=160 -> 128 ----
    {
        const int F = 160, F4 = F / 4;
        int total = EE * F4;
        zero_kernel<<<CDIV(NN * F / 4, T), T>>>((float4*)pT1, NN * F / 4);
        propagate_kernel<<<CDIV(total, T), T>>>(x, pT1, src, dst, F4, total);
        zero_kernel<<<CDIV(NN * F / 4, T), T>>>((float4*)pT2, NN * F / 4);
        propagate_kernel<<<CDIV(total, T), T>>>(pT1, pT2, src, dst, F4, total);
        gemm_relu_kernel<128><<<CDIV(NN, 128), 256>>>(x, pT1, pT2, pWm1, b1, pH1, NN, F, 1);
    }
    // ---- layer 2: F=128 -> 64 ----
    {
        const int F = 128, F4 = F / 4;
        int total = EE * F4;
        zero_kernel<<<CDIV(NN * F / 4, T), T>>>((float4*)pT1, NN * F / 4);
        propagate_kernel<<<CDIV(total, T), T>>>(pH1, pT1, src, dst, F4, total);
        zero_kernel<<<CDIV(NN * F / 4, T), T>>>((float4*)pT2, NN * F / 4);
        propagate_kernel<<<CDIV(total, T), T>>>(pT1, pT2, src, dst, F4, total);
        gemm_relu_kernel<64><<<CDIV(NN, 128), 256>>>(pH1, pT1, pT2, pWm2, b2, pH2, NN, F, 1);
    }
    // ---- layer 3: F=64 -> 32 ----
    {
        const int F = 64, F4 = F / 4;
        int total = EE * F4;
        zero_kernel<<<CDIV(NN * F / 4, T), T>>>((float4*)pT1, NN * F / 4);
        propagate_kernel<<<CDIV(total, T), T>>>(pH2, pT1, src, dst, F4, total);
        zero_kernel<<<CDIV(NN * F / 4, T), T>>>((float4*)pT2, NN * F / 4);
        propagate_kernel<<<CDIV(total, T), T>>>(pT1, pT2, src, dst, F4, total);
        gemm_relu_kernel<32><<<CDIV(NN, 128), 256>>>(pH2, pT1, pT2, pWm3, b3, pH3, NN, F, 1);
    }

    // ---- pool + final linear ----
    zero_kernel<<<CDIV(NG * 32 / 4, T), T>>>((float4*)ppool, NG * 32 / 4);
    zero_kernel<<<1, T>>>((float4*)pcnt, NG / 4);
    pool_kernel<<<CDIV(NN * 32, T), T>>>(batch);
    final_kernel<<<1, 256>>>(Wl, bl, (float*)d_out);
}

// round 2
// speedup vs baseline: 1.0621x; 1.0621x over previous
#include <cuda_runtime.h>
#include <cstdint>

#define NN 50000
#define EE 500000
#define FIN 160
#define NG  128

#define CDIV(a,b) (((a)+(b)-1)/(b))

// ---------------- device scratch (no allocation allowed) ----------------
__device__ __align__(16) float g_w[EE];
__device__ __align__(16) float g_dinv[NN];
__device__ __align__(16) float g_T1[NN * FIN];
__device__ __align__(16) float g_T2[NN * FIN];
__device__ __align__(16) float g_H1[NN * 128];
__device__ __align__(16) float g_H2[NN * 64];
__device__ __align__(16) float g_H3[NN * 32];
__device__ __align__(16) float g_Wm1[3 * 160 * 128];
__device__ __align__(16) float g_Wm2[3 * 128 * 64];
__device__ __align__(16) float g_Wm3[3 * 64 * 32];
__device__ __align__(16) float g_pool[NG * 32];
__device__ __align__(16) float g_cnt[NG];

// ---------------- helpers ----------------
__device__ __forceinline__ void red_add_v4(float* addr, float4 v) {
    asm volatile("red.global.add.v4.f32 [%0], {%1,%2,%3,%4};"
                 :: "l"(addr), "f"(v.x), "f"(v.y), "f"(v.z), "f"(v.w)
                 : "memory");
}

__device__ __forceinline__ float tf32_hi(float x) {
    uint32_t u;
    asm("cvt.rna.tf32.f32 %0, %1;" : "=r"(u) : "f"(x));
    return __uint_as_float(u);
}

__device__ __forceinline__ void mma_tf32(float* c, const uint32_t* a, const uint32_t* b) {
    asm volatile("mma.sync.aligned.m16n8k8.row.col.f32.tf32.tf32.f32 "
                 "{%0,%1,%2,%3}, {%4,%5,%6,%7}, {%8,%9}, {%0,%1,%2,%3};"
                 : "+f"(c[0]), "+f"(c[1]), "+f"(c[2]), "+f"(c[3])
                 : "r"(a[0]), "r"(a[1]), "r"(a[2]), "r"(a[3]),
                   "r"(b[0]), "r"(b[1]));
}

__global__ void zero_kernel(float4* __restrict__ p, int n4) {
    int i = blockIdx.x * blockDim.x + threadIdx.x;
    if (i < n4) p[i] = make_float4(0.f, 0.f, 0.f, 0.f);
}

// ---------------- graph normalization ----------------
__global__ void deg_kernel(const int* __restrict__ src, const float* __restrict__ ea) {
    int e = blockIdx.x * blockDim.x + threadIdx.x;
    if (e < EE) atomicAdd(&g_dinv[src[e]], ea[e]);
}

__global__ void dinv_kernel() {
    int i = blockIdx.x * blockDim.x + threadIdx.x;
    if (i < NN) {
        float d = g_dinv[i];
        g_dinv[i] = (d > 0.f) ? rsqrtf(d) : 0.f;
    }
}

__global__ void w_kernel(const int* __restrict__ src, const int* __restrict__ dst,
                         const float* __restrict__ ea) {
    int e = blockIdx.x * blockDim.x + threadIdx.x;
    if (e < EE) g_w[e] = -g_dinv[src[e]] * ea[e] * g_dinv[dst[e]];
}

// ---------------- weight prep: Wm = [W0 - W2, W1, 2*W2] ----------------
__global__ void wprep_kernel(const float* __restrict__ W, float* __restrict__ Wm, int FFout) {
    int t = blockIdx.x * blockDim.x + threadIdx.x;
    if (t >= 3 * FFout) return;
    int k = t / FFout;
    int rel = t - k * FFout;
    float v = W[t];
    float out;
    if (k == 0)      out = v - W[2 * FFout + rel];
    else if (k == 1) out = v;
    else             out = 2.f * v;
    Wm[t] = out;
}

// ---------------- sparse propagate: out[dst] += w * X[src] ----------------
__global__ void propagate_kernel(const float* __restrict__ X, float* __restrict__ out,
                                 const int* __restrict__ src, const int* __restrict__ dst,
                                 int F4, int total) {
    int t = blockIdx.x * blockDim.x + threadIdx.x;
    if (t >= total) return;
    int e = t / F4;
    int c = t - e * F4;
    float we = g_w[e];
    int s = src[e];
    int d = dst[e];
    float4 v = ((const float4*)X)[(size_t)s * F4 + c];
    float4 r = make_float4(we * v.x, we * v.y, we * v.z, we * v.w);
    red_add_v4(out + ((size_t)d * F4 + c) * 4, r);
}

// ---------------- TF32 tensor-core GEMM with hi/lo split ----------------
// C = relu([A0|A1|A2] (M x 3F) @ B (3F x BN) + bias)
// BM=128, BK=16, 256 threads (8 warps). Full fp32 accuracy via 3-term tf32.
template <int BN>
__launch_bounds__(256, 2)
__global__ void gemm_tc_kernel(const float* __restrict__ A0,
                               const float* __restrict__ A1,
                               const float* __restrict__ A2,
                               const float* __restrict__ B,
                               const float* __restrict__ bias,
                               float* __restrict__ C,
                               int M, int F, int do_relu) {
    const int BM = 128, BK = 16;
    const int WARPS_N = BN / 32;        // 4 / 2 / 1
    const int WARPS_M = 8 / WARPS_N;    // 2 / 4 / 8
    const int WM = BM / WARPS_M;        // 64 / 32 / 16
    const int TM = WM / 16;             // 4 / 2 / 1
    const int TN = 4;                   // 32 / 8

    __shared__ float As_hi[BM][BK + 4];   // stride 20 floats, conflict-free frag loads
    __shared__ float As_lo[BM][BK + 4];
    __shared__ float Bs_hi[BK][BN + 4];
    __shared__ float Bs_lo[BK][BN + 4];

    int t = threadIdx.x;
    int warp = t >> 5, lane = t & 31;
    int group = lane >> 2, tg = lane & 3;
    int warp_m = warp % WARPS_M;
    int warp_n = warp / WARPS_M;
    int m_w = warp_m * WM;
    int n_w = warp_n * 32;
    int m0 = blockIdx.x * BM;
    int K = 3 * F;

    float acc[TM][TN][4];
#pragma unroll
    for (int i = 0; i < TM; ++i)
#pragma unroll
        for (int j = 0; j < TN; ++j)
#pragma unroll
            for (int r = 0; r < 4; ++r) acc[i][j][r] = 0.f;

    for (int k0 = 0; k0 < K; k0 += BK) {
        int seg = k0 / F;    // F % 16 == 0 so tile never crosses segments
        const float* A = (seg == 0) ? A0 : ((seg == 1) ? A1 : A2);
        int kc = k0 - seg * F;

        // ---- load A tile (128x16): 512 float4, 2 per thread, hi/lo split at store
#pragma unroll
        for (int l = 0; l < 2; ++l) {
            int idx = t + l * 256;
            int row = idx >> 2;
            int c4 = (idx & 3) * 4;
            float4 v = make_float4(0.f, 0.f, 0.f, 0.f);
            int m = m0 + row;
            if (m < M) v = *(const float4*)(A + (size_t)m * F + kc + c4);
            float hx = tf32_hi(v.x), hy = tf32_hi(v.y), hz = tf32_hi(v.z), hw = tf32_hi(v.w);
            *(float4*)&As_hi[row][c4] = make_float4(hx, hy, hz, hw);
            *(float4*)&As_lo[row][c4] = make_float4(tf32_hi(v.x - hx), tf32_hi(v.y - hy),
                                                    tf32_hi(v.z - hz), tf32_hi(v.w - hw));
        }
        // ---- load B tile (16xBN)
        for (int idx = t; idx < BK * BN / 4; idx += 256) {
            int row = idx / (BN / 4);
            int c4 = (idx % (BN / 4)) * 4;
            float4 v = *(const float4*)(B + (size_t)(k0 + row) * BN + c4);
            float hx = tf32_hi(v.x), hy = tf32_hi(v.y), hz = tf32_hi(v.z), hw = tf32_hi(v.w);
            *(float4*)&Bs_hi[row][c4] = make_float4(hx, hy, hz, hw);
            *(float4*)&Bs_lo[row][c4] = make_float4(tf32_hi(v.x - hx), tf32_hi(v.y - hy),
                                                    tf32_hi(v.z - hz), tf32_hi(v.w - hw));
        }
        __syncthreads();

#pragma unroll
        for (int ks = 0; ks < 2; ++ks) {
            int kb = ks * 8;
            uint32_t bh[TN][2], bl[TN][2];
#pragma unroll
            for (int j = 0; j < TN; ++j) {
                int n = n_w + j * 8 + group;
                bh[j][0] = __float_as_uint(Bs_hi[kb + tg][n]);
                bh[j][1] = __float_as_uint(Bs_hi[kb + tg + 4][n]);
                bl[j][0] = __float_as_uint(Bs_lo[kb + tg][n]);
                bl[j][1] = __float_as_uint(Bs_lo[kb + tg + 4][n]);
            }
#pragma unroll
            for (int i = 0; i < TM; ++i) {
                int mb = m_w + i * 16;
                uint32_t ah[4], al[4];
                ah[0] = __float_as_uint(As_hi[mb + group][kb + tg]);
                ah[1] = __float_as_uint(As_hi[mb + group + 8][kb + tg]);
                ah[2] = __float_as_uint(As_hi[mb + group][kb + tg + 4]);
                ah[3] = __float_as_uint(As_hi[mb + group + 8][kb + tg + 4]);
                al[0] = __float_as_uint(As_lo[mb + group][kb + tg]);
                al[1] = __float_as_uint(As_lo[mb + group + 8][kb + tg]);
                al[2] = __float_as_uint(As_lo[mb + group][kb + tg + 4]);
                al[3] = __float_as_uint(As_lo[mb + group + 8][kb + tg + 4]);
#pragma unroll
                for (int j = 0; j < TN; ++j) {
                    mma_tf32(acc[i][j], ah, bh[j]);   // hi*hi
                    mma_tf32(acc[i][j], ah, bl[j]);   // hi*lo
                    mma_tf32(acc[i][j], al, bh[j]);   // lo*hi
                }
            }
        }
        __syncthreads();
    }

    // ---- epilogue: bias + relu + store
#pragma unroll
    for (int i = 0; i < TM; ++i) {
        int mb = m0 + m_w + i * 16;
        int row0 = mb + group;
        int row1 = mb + group + 8;
#pragma unroll
        for (int j = 0; j < TN; ++j) {
            int n = n_w + j * 8 + 2 * tg;
            float bz0 = bias[n], bz1 = bias[n + 1];
            if (row0 < M) {
                float v0 = acc[i][j][0] + bz0;
                float v1 = acc[i][j][1] + bz1;
                if (do_relu) { v0 = fmaxf(v0, 0.f); v1 = fmaxf(v1, 0.f); }
                C[(size_t)row0 * BN + n] = v0;
                C[(size_t)row0 * BN + n + 1] = v1;
            }
            if (row1 < M) {
                float v2 = acc[i][j][2] + bz0;
                float v3 = acc[i][j][3] + bz1;
                if (do_relu) { v2 = fmaxf(v2, 0.f); v3 = fmaxf(v3, 0.f); }
                C[(size_t)row1 * BN + n] = v2;
                C[(size_t)row1 * BN + n + 1] = v3;
            }
        }
    }
}

// ---------------- pooling + final linear ----------------
__global__ void pool_kernel(const int* __restrict__ batch) {
    int t = blockIdx.x * blockDim.x + threadIdx.x;
    if (t >= NN * 32) return;
    int i = t >> 5;
    int c = t & 31;
    int g = batch[i];
    atomicAdd(&g_pool[g * 32 + c], g_H3[t]);
    if (c == 0) atomicAdd(&g_cnt[g], 1.0f);
}

__global__ void final_kernel(const float* __restrict__ Wl, const float* __restrict__ bl,
                             float* __restrict__ out) {
    int t = threadIdx.x;
    if (t >= NG * 2) return;
    int g = t >> 1;
    int j = t & 1;
    float cnt = fmaxf(g_cnt[g], 1.0f);
    float s = 0.f;
#pragma unroll
    for (int c = 0; c < 32; ++c) s += g_pool[g * 32 + c] * Wl[c * 2 + j];
    out[t] = s / cnt + bl[j];
}

// ---------------- host orchestration ----------------
extern "C" void kernel_launch(void* const* d_in, const int* in_sizes, int n_in,
                              void* d_out, int out_size) {
    const float* x     = (const float*)d_in[0];
    const int*   ei    = (const int*)d_in[1];
    const float* ea    = (const float*)d_in[2];
    const int*   batch = (const int*)d_in[3];
    const float* W1    = (const float*)d_in[4];
    const float* b1    = (const float*)d_in[5];
    const float* W2    = (const float*)d_in[6];
    const float* b2    = (const float*)d_in[7];
    const float* W3    = (const float*)d_in[8];
    const float* b3    = (const float*)d_in[9];
    const float* Wl    = (const float*)d_in[10];
    const float* bl    = (const float*)d_in[11];
    const int* src = ei;
    const int* dst = ei + EE;

    float *pT1, *pT2, *pH1, *pH2, *pH3, *pWm1, *pWm2, *pWm3, *pdinv, *ppool, *pcnt;
    cudaGetSymbolAddress((void**)&pT1,  g_T1);
    cudaGetSymbolAddress((void**)&pT2,  g_T2);
    cudaGetSymbolAddress((void**)&pH1,  g_H1);
    cudaGetSymbolAddress((void**)&pH2,  g_H2);
    cudaGetSymbolAddress((void**)&pH3,  g_H3);
    cudaGetSymbolAddress((void**)&pWm1, g_Wm1);
    cudaGetSymbolAddress((void**)&pWm2, g_Wm2);
    cudaGetSymbolAddress((void**)&pWm3, g_Wm3);
    cudaGetSymbolAddress((void**)&pdinv, g_dinv);
    cudaGetSymbolAddress((void**)&ppool, g_pool);
    cudaGetSymbolAddress((void**)&pcnt,  g_cnt);

    const int T = 256;

    // normalization weights: deg -> dinv -> w
    zero_kernel<<<CDIV(NN / 4, T), T>>>((float4*)pdinv, NN / 4);
    deg_kernel<<<CDIV(EE, T), T>>>(src, ea);
    dinv_kernel<<<CDIV(NN, T), T>>>();
    w_kernel<<<CDIV(EE, T), T>>>(src, dst, ea);

    // modified weights per layer
    wprep_kernel<<<CDIV(3 * 160 * 128, T), T>>>(W1, pWm1, 160 * 128);
    wprep_kernel<<<CDIV(3 * 128 * 64, T), T>>>(W2, pWm2, 128 * 64);
    wprep_kernel<<<CDIV(3 * 64 * 32, T), T>>>(W3, pWm3, 64 * 32);

    // ---- layer 1: F=160 -> 128 ----
    {
        const int F = 160, F4 = F / 4;
        int total = EE * F4;
        zero_kernel<<<CDIV(NN * F / 4, T), T>>>((float4*)pT1, NN * F / 4);
        propagate_kernel<<<CDIV(total, T), T>>>(x, pT1, src, dst, F4, total);
        zero_kernel<<<CDIV(NN * F / 4, T), T>>>((float4*)pT2, NN * F / 4);
        propagate_kernel<<<CDIV(total, T), T>>>(pT1, pT2, src, dst, F4, total);
        gemm_tc_kernel<128><<<CDIV(NN, 128), 256>>>(x, pT1, pT2, pWm1, b1, pH1, NN, F, 1);
    }
    // ---- layer 2: F=128 -> 64 ----
    {
        const int F = 128, F4 = F / 4;
        int total = EE * F4;
        zero_kernel<<<CDIV(NN * F / 4, T), T>>>((float4*)pT1, NN * F / 4);
        propagate_kernel<<<CDIV(total, T), T>>>(pH1, pT1, src, dst, F4, total);
        zero_kernel<<<CDIV(NN * F / 4, T), T>>>((float4*)pT2, NN * F / 4);
        propagate_kernel<<<CDIV(total, T), T>>>(pT1, pT2, src, dst, F4, total);
        gemm_tc_kernel<64><<<CDIV(NN, 128), 256>>>(pH1, pT1, pT2, pWm2, b2, pH2, NN, F, 1);
    }
    // ---- layer 3: F=64 -> 32 ----
    {
        const int F = 64, F4 = F / 4;
        int total = EE * F4;
        zero_kernel<<<CDIV(NN * F / 4, T), T>>>((float4*)pT1, NN * F / 4);
        propagate_kernel<<<CDIV(total, T), T>>>(pH2, pT1, src, dst, F4, total);
        zero_kernel<<<CDIV(NN * F / 4, T), T>>>((float4*)pT2, NN * F / 4);
        propagate_kernel<<<CDIV(total, T), T>>>(pT1, pT2, src, dst, F4, total);
        gemm_tc_kernel<32><<<CDIV(NN, 128), 256>>>(pH2, pT1, pT2, pWm3, b3, pH3, NN, F, 1);
    }

    // ---- pool + final linear ----
    zero_kernel<<<CDIV(NG * 32 / 4, T), T>>>((float4*)ppool, NG * 32 / 4);
    zero_kernel<<<1, T>>>((float4*)pcnt, NG / 4);
    pool_kernel<<<CDIV(NN * 32, T), T>>>(batch);
    final_kernel<<<1, 256>>>(Wl, bl, (float*)d_out);
}

// round 3
// speedup vs baseline: 1.4040x; 1.3219x over previous
#include <cuda_runtime.h>
#include <cstdint>

#define NN 50000
#define EE 500000
#define NG  128

#define CDIV(a,b) (((a)+(b)-1)/(b))

// ---------------- device scratch (no allocation allowed) ----------------
__device__ __align__(16) float g_w[EE];
__device__ __align__(16) float g_dinv[NN];
__device__ __align__(16) float g_cat[NN * 384];     // [Y0 | V | V2], ld = 3*F_out (max 384)
__device__ __align__(16) float g_H1[NN * 128];
__device__ __align__(16) float g_H2[NN * 64];
__device__ __align__(16) float g_H3[NN * 32];
__device__ __align__(16) float g_Wc1[160 * 384];
__device__ __align__(16) float g_Wc2[128 * 192];
__device__ __align__(16) float g_Wc3[64 * 96];
__device__ __align__(16) float g_pool[NG * 32];
__device__ __align__(16) float g_cnt[NG];

// ---------------- helpers ----------------
__device__ __forceinline__ void red_add_v4(float* addr, float4 v) {
    asm volatile("red.global.add.v4.f32 [%0], {%1,%2,%3,%4};"
                 :: "l"(addr), "f"(v.x), "f"(v.y), "f"(v.z), "f"(v.w)
                 : "memory");
}

__device__ __forceinline__ float tf32_hi(float x) {
    uint32_t u;
    asm("cvt.rna.tf32.f32 %0, %1;" : "=r"(u) : "f"(x));
    return __uint_as_float(u);
}

__device__ __forceinline__ void mma_tf32(float* c, const uint32_t* a, const uint32_t* b) {
    asm volatile("mma.sync.aligned.m16n8k8.row.col.f32.tf32.tf32.f32 "
                 "{%0,%1,%2,%3}, {%4,%5,%6,%7}, {%8,%9}, {%0,%1,%2,%3};"
                 : "+f"(c[0]), "+f"(c[1]), "+f"(c[2]), "+f"(c[3])
                 : "r"(a[0]), "r"(a[1]), "r"(a[2]), "r"(a[3]),
                   "r"(b[0]), "r"(b[1]));
}

__global__ void zero_kernel(float4* __restrict__ p, int n4) {
    int i = blockIdx.x * blockDim.x + threadIdx.x;
    if (i < n4) p[i] = make_float4(0.f, 0.f, 0.f, 0.f);
}

// ---------------- graph normalization ----------------
__global__ void deg_kernel(const int* __restrict__ src, const float* __restrict__ ea) {
    int e = blockIdx.x * blockDim.x + threadIdx.x;
    if (e < EE) atomicAdd(&g_dinv[src[e]], ea[e]);
}

__global__ void dinv_kernel() {
    int i = blockIdx.x * blockDim.x + threadIdx.x;
    if (i < NN) {
        float d = g_dinv[i];
        g_dinv[i] = (d > 0.f) ? rsqrtf(d) : 0.f;
    }
}

__global__ void w_kernel(const int* __restrict__ src, const int* __restrict__ dst,
                         const float* __restrict__ ea) {
    int e = blockIdx.x * blockDim.x + threadIdx.x;
    if (e < EE) g_w[e] = -g_dinv[src[e]] * ea[e] * g_dinv[dst[e]];
}

// ---------------- weight prep: Wcat[f][0:G]=W0-W2, [G:2G]=W1, [2G:3G]=2*W2 ----------------
__global__ void wprep_kernel(const float* __restrict__ W, float* __restrict__ Wc,
                             int F, int G) {
    int t = blockIdx.x * blockDim.x + threadIdx.x;
    if (t >= F * G) return;
    int f = t / G;
    int c = t - f * G;
    float w0 = W[t];
    float w1 = W[F * G + t];
    float w2 = W[2 * F * G + t];
    Wc[f * 3 * G + c]         = w0 - w2;
    Wc[f * 3 * G + G + c]     = w1;
    Wc[f * 3 * G + 2 * G + c] = 2.f * w2;
}

// ---------------- strided sparse propagate within the cat buffer ----------------
// out[dst*ld4 + dstoff + c] += w * X[src*ld4 + srcoff + c]   (float4 units)
__global__ void prop_kernel(const float* __restrict__ X, float* __restrict__ out,
                            const int* __restrict__ src, const int* __restrict__ dst,
                            int F4, int ld4, int srcoff4, int dstoff4, int total) {
    int t = blockIdx.x * blockDim.x + threadIdx.x;
    if (t >= total) return;
    int e = t / F4;
    int c = t - e * F4;
    float we = g_w[e];
    int s = src[e];
    int d = dst[e];
    float4 v = ((const float4*)X)[(size_t)s * ld4 + srcoff4 + c];
    float4 r = make_float4(we * v.x, we * v.y, we * v.z, we * v.w);
    red_add_v4(out + ((size_t)d * ld4 + dstoff4 + c) * 4, r);
}

// ---------------- bias + relu epilogue: H[i][c] = relu(cat[i][c] + b[c]) ----------------
__global__ void bias_relu_kernel(const float* __restrict__ cat, const float* __restrict__ bias,
                                 float* __restrict__ H, int G4, int ld4, int total) {
    int t = blockIdx.x * blockDim.x + threadIdx.x;
    if (t >= total) return;
    int i = t / G4;
    int c = t - i * G4;
    float4 v = ((const float4*)cat)[(size_t)i * ld4 + c];
    float4 b = ((const float4*)bias)[c];
    float4 o;
    o.x = fmaxf(v.x + b.x, 0.f);
    o.y = fmaxf(v.y + b.y, 0.f);
    o.z = fmaxf(v.z + b.z, 0.f);
    o.w = fmaxf(v.w + b.w, 0.f);
    ((float4*)H)[(size_t)i * G4 + c] = o;
}

// ---------------- TF32 tensor-core GEMM (hi/lo 3-term), tiled in N ----------------
// C[m][n0+n] = sum_k A[m][k] * B[k][n0+n];  B/C have leading dim ldn = 3*G.
// grid.y selects the 128/64/32-wide column tile (n0 = blockIdx.y * BN).
template <int BN>
__launch_bounds__(256, 2)
__global__ void gemm_tc_kernel(const float* __restrict__ A,
                               const float* __restrict__ B,
                               float* __restrict__ C,
                               int M, int F, int ldn) {
    const int BM = 128, BK = 16;
    const int WARPS_N = BN / 32;        // 4 / 2 / 1
    const int WARPS_M = 8 / WARPS_N;    // 2 / 4 / 8
    const int WM = BM / WARPS_M;        // 64 / 32 / 16
    const int TM = WM / 16;             // 4 / 2 / 1
    const int TN = 4;

    __shared__ float As_hi[BM][BK + 4];
    __shared__ float As_lo[BM][BK + 4];
    __shared__ float Bs_hi[BK][BN + 4];
    __shared__ float Bs_lo[BK][BN + 4];

    int t = threadIdx.x;
    int warp = t >> 5, lane = t & 31;
    int group = lane >> 2, tg = lane & 3;
    int warp_m = warp % WARPS_M;
    int warp_n = warp / WARPS_M;
    int m_w = warp_m * WM;
    int n_w = warp_n * 32;
    int m0 = blockIdx.x * BM;
    int n0 = blockIdx.y * BN;

    float acc[TM][TN][4];
#pragma unroll
    for (int i = 0; i < TM; ++i)
#pragma unroll
        for (int j = 0; j < TN; ++j)
#pragma unroll
            for (int r = 0; r < 4; ++r) acc[i][j][r] = 0.f;

    for (int k0 = 0; k0 < F; k0 += BK) {
        // ---- A tile (128x16), hi/lo split at store
#pragma unroll
        for (int l = 0; l < 2; ++l) {
            int idx = t + l * 256;
            int row = idx >> 2;
            int c4 = (idx & 3) * 4;
            float4 v = make_float4(0.f, 0.f, 0.f, 0.f);
            int m = m0 + row;
            if (m < M) v = *(const float4*)(A + (size_t)m * F + k0 + c4);
            float hx = tf32_hi(v.x), hy = tf32_hi(v.y), hz = tf32_hi(v.z), hw = tf32_hi(v.w);
            *(float4*)&As_hi[row][c4] = make_float4(hx, hy, hz, hw);
            *(float4*)&As_lo[row][c4] = make_float4(tf32_hi(v.x - hx), tf32_hi(v.y - hy),
                                                    tf32_hi(v.z - hz), tf32_hi(v.w - hw));
        }
        // ---- B tile (16xBN)
        for (int idx = t; idx < BK * BN / 4; idx += 256) {
            int row = idx / (BN / 4);
            int c4 = (idx % (BN / 4)) * 4;
            float4 v = *(const float4*)(B + (size_t)(k0 + row) * ldn + n0 + c4);
            float hx = tf32_hi(v.x), hy = tf32_hi(v.y), hz = tf32_hi(v.z), hw = tf32_hi(v.w);
            *(float4*)&Bs_hi[row][c4] = make_float4(hx, hy, hz, hw);
            *(float4*)&Bs_lo[row][c4] = make_float4(tf32_hi(v.x - hx), tf32_hi(v.y - hy),
                                                    tf32_hi(v.z - hz), tf32_hi(v.w - hw));
        }
        __syncthreads();

#pragma unroll
        for (int ks = 0; ks < 2; ++ks) {
            int kb = ks * 8;
            uint32_t bh[TN][2], bl[TN][2];
#pragma unroll
            for (int j = 0; j < TN; ++j) {
                int n = n_w + j * 8 + group;
                bh[j][0] = __float_as_uint(Bs_hi[kb + tg][n]);
                bh[j][1] = __float_as_uint(Bs_hi[kb + tg + 4][n]);
                bl[j][0] = __float_as_uint(Bs_lo[kb + tg][n]);
                bl[j][1] = __float_as_uint(Bs_lo[kb + tg + 4][n]);
            }
#pragma unroll
            for (int i = 0; i < TM; ++i) {
                int mb = m_w + i * 16;
                uint32_t ah[4], al[4];
                ah[0] = __float_as_uint(As_hi[mb + group][kb + tg]);
                ah[1] = __float_as_uint(As_hi[mb + group + 8][kb + tg]);
                ah[2] = __float_as_uint(As_hi[mb + group][kb + tg + 4]);
                ah[3] = __float_as_uint(As_hi[mb + group + 8][kb + tg + 4]);
                al[0] = __float_as_uint(As_lo[mb + group][kb + tg]);
                al[1] = __float_as_uint(As_lo[mb + group + 8][kb + tg]);
                al[2] = __float_as_uint(As_lo[mb + group][kb + tg + 4]);
                al[3] = __float_as_uint(As_lo[mb + group + 8][kb + tg + 4]);
#pragma unroll
                for (int j = 0; j < TN; ++j) {
                    mma_tf32(acc[i][j], ah, bh[j]);
                    mma_tf32(acc[i][j], ah, bl[j]);
                    mma_tf32(acc[i][j], al, bh[j]);
                }
            }
        }
        __syncthreads();
    }

    // ---- store (no bias/relu here)
#pragma unroll
    for (int i = 0; i < TM; ++i) {
        int mb = m0 + m_w + i * 16;
        int row0 = mb + group;
        int row1 = mb + group + 8;
#pragma unroll
        for (int j = 0; j < TN; ++j) {
            int n = n0 + n_w + j * 8 + 2 * tg;
            if (row0 < M) {
                C[(size_t)row0 * ldn + n]     = acc[i][j][0];
                C[(size_t)row0 * ldn + n + 1] = acc[i][j][1];
            }
            if (row1 < M) {
                C[(size_t)row1 * ldn + n]     = acc[i][j][2];
                C[(size_t)row1 * ldn + n + 1] = acc[i][j][3];
            }
        }
    }
}

// ---------------- pooling + final linear ----------------
__global__ void pool_kernel(const int* __restrict__ batch) {
    int t = blockIdx.x * blockDim.x + threadIdx.x;
    if (t >= NN * 32) return;
    int i = t >> 5;
    int c = t & 31;
    int g = batch[i];
    atomicAdd(&g_pool[g * 32 + c], g_H3[t]);
    if (c == 0) atomicAdd(&g_cnt[g], 1.0f);
}

__global__ void final_kernel(const float* __restrict__ Wl, const float* __restrict__ bl,
                             float* __restrict__ out) {
    int t = threadIdx.x;
    if (t >= NG * 2) return;
    int g = t >> 1;
    int j = t & 1;
    float cnt = fmaxf(g_cnt[g], 1.0f);
    float s = 0.f;
#pragma unroll
    for (int c = 0; c < 32; ++c) s += g_pool[g * 32 + c] * Wl[c * 2 + j];
    out[t] = s / cnt + bl[j];
}

// ---------------- one Cheb layer ----------------
// A (N x F, relu'd input), Wc (F x 3G), bias (G), H (N x G output)
static void run_layer(const float* A, const float* Wc, const float* bias, float* H,
                      float* cat, const int* src, const int* dst, int F, int G) {
    const int T = 256;
    int ld = 3 * G, ld4 = ld / 4, G4 = G / 4;
    // GEMM: cat = A @ Wc   ([Y0 | V | V2])
    dim3 grid(CDIV(NN, 128), 3);
    if (G == 128)      gemm_tc_kernel<128><<<grid, 256>>>(A, Wc, cat, NN, F, ld);
    else if (G == 64)  gemm_tc_kernel<64><<<grid, 256>>>(A, Wc, cat, NN, F, ld);
    else               gemm_tc_kernel<32><<<grid, 256>>>(A, Wc, cat, NN, F, ld);
    // Z = V + P V2  (red.add into V region, reading V2 region)
    int total = EE * G4;
    prop_kernel<<<CDIV(total, T), T>>>(cat, cat, src, dst, G4, ld4, 2 * G4, G4, total);
    // Y0 += P Z     (red.add into Y0 region, reading V region)
    prop_kernel<<<CDIV(total, T), T>>>(cat, cat, src, dst, G4, ld4, G4, 0, total);
    // H = relu(Y0 + bias)
    int etotal = NN * G4;
    bias_relu_kernel<<<CDIV(etotal, T), T>>>(cat, bias, H, G4, ld4, etotal);
}

// ---------------- host orchestration ----------------
extern "C" void kernel_launch(void* const* d_in, const int* in_sizes, int n_in,
                              void* d_out, int out_size) {
    const float* x     = (const float*)d_in[0];
    const int*   ei    = (const int*)d_in[1];
    const float* ea    = (const float*)d_in[2];
    const int*   batch = (const int*)d_in[3];
    const float* W1    = (const float*)d_in[4];
    const float* b1    = (const float*)d_in[5];
    const float* W2    = (const float*)d_in[6];
    const float* b2    = (const float*)d_in[7];
    const float* W3    = (const float*)d_in[8];
    const float* b3    = (const float*)d_in[9];
    const float* Wl    = (const float*)d_in[10];
    const float* bl    = (const float*)d_in[11];
    const int* src = ei;
    const int* dst = ei + EE;

    float *pcat, *pH1, *pH2, *pH3, *pWc1, *pWc2, *pWc3, *pdinv, *ppool, *pcnt;
    cudaGetSymbolAddress((void**)&pcat, g_cat);
    cudaGetSymbolAddress((void**)&pH1,  g_H1);
    cudaGetSymbolAddress((void**)&pH2,  g_H2);
    cudaGetSymbolAddress((void**)&pH3,  g_H3);
    cudaGetSymbolAddress((void**)&pWc1, g_Wc1);
    cudaGetSymbolAddress((void**)&pWc2, g_Wc2);
    cudaGetSymbolAddress((void**)&pWc3, g_Wc3);
    cudaGetSymbolAddress((void**)&pdinv, g_dinv);
    cudaGetSymbolAddress((void**)&ppool, g_pool);
    cudaGetSymbolAddress((void**)&pcnt,  g_cnt);

    const int T = 256;

    // normalization weights
    zero_kernel<<<CDIV(NN / 4, T), T>>>((float4*)pdinv, NN / 4);
    deg_kernel<<<CDIV(EE, T), T>>>(src, ea);
    dinv_kernel<<<CDIV(NN, T), T>>>();
    w_kernel<<<CDIV(EE, T), T>>>(src, dst, ea);

    // concatenated modified weights
    wprep_kernel<<<CDIV(160 * 128, T), T>>>(W1, pWc1, 160, 128);
    wprep_kernel<<<CDIV(128 * 64, T), T>>>(W2, pWc2, 128, 64);
    wprep_kernel<<<CDIV(64 * 32, T), T>>>(W3, pWc3, 64, 32);

    run_layer(x,   pWc1, b1, pH1, pcat, src, dst, 160, 128);
    run_layer(pH1, pWc2, b2, pH2, pcat, src, dst, 128, 64);
    run_layer(pH2, pWc3, b3, pH3, pcat, src, dst, 64, 32);

    // pool + final linear
    zero_kernel<<<CDIV(NG * 32 / 4, T), T>>>((float4*)ppool, NG * 32 / 4);
    zero_kernel<<<1, T>>>((float4*)pcnt, NG / 4);
    pool_kernel<<<CDIV(NN * 32, T), T>>>(batch);
    final_kernel<<<1, 256>>>(Wl, bl, (float*)d_out);
}

// round 4
// speedup vs baseline: 1.5682x; 1.1169x over previous
#include <cuda_runtime.h>
#include <cstdint>

#define NN 50000
#define EE 500000
#define NG  128

#define CDIV(a,b) (((a)+(b)-1)/(b))

// ---------------- device scratch (no allocation allowed) ----------------
__device__ __align__(16) float g_w[EE];
__device__ __align__(16) float g_dinv[NN];
__device__ __align__(16) float g_cat[NN * 384];     // [Y0 | V | V2], ld = 3*G
__device__ __align__(16) float g_H1[NN * 128];
__device__ __align__(16) float g_H2[NN * 64];
__device__ __align__(16) float g_Wc1[160 * 384];
__device__ __align__(16) float g_Wc2[128 * 192];
__device__ __align__(16) float g_Wc3[64 * 96];
__device__ __align__(16) float g_pool[NG * 32];
__device__ __align__(16) float g_cnt[NG];
// CSR (indexed by dst)
__device__ int   g_rowptr[NN + 1];
__device__ int   g_fill[NN];
__device__ __align__(16) int   g_csr_src[EE];
__device__ __align__(16) float g_csr_w[EE];

// ---------------- helpers ----------------
__device__ __forceinline__ void red_add_v4(float* addr, float4 v) {
    asm volatile("red.global.add.v4.f32 [%0], {%1,%2,%3,%4};"
                 :: "l"(addr), "f"(v.x), "f"(v.y), "f"(v.z), "f"(v.w)
                 : "memory");
}

__device__ __forceinline__ float tf32_hi(float x) {
    uint32_t u;
    asm("cvt.rna.tf32.f32 %0, %1;" : "=r"(u) : "f"(x));
    return __uint_as_float(u);
}

__device__ __forceinline__ void mma_tf32(float* c, const uint32_t* a, const uint32_t* b) {
    asm volatile("mma.sync.aligned.m16n8k8.row.col.f32.tf32.tf32.f32 "
                 "{%0,%1,%2,%3}, {%4,%5,%6,%7}, {%8,%9}, {%0,%1,%2,%3};"
                 : "+f"(c[0]), "+f"(c[1]), "+f"(c[2]), "+f"(c[3])
                 : "r"(a[0]), "r"(a[1]), "r"(a[2]), "r"(a[3]),
                   "r"(b[0]), "r"(b[1]));
}

__global__ void zero_kernel(float4* __restrict__ p, int n4) {
    int i = blockIdx.x * blockDim.x + threadIdx.x;
    if (i < n4) p[i] = make_float4(0.f, 0.f, 0.f, 0.f);
}

__global__ void zeroi_kernel(int* __restrict__ p, int n) {
    int i = blockIdx.x * blockDim.x + threadIdx.x;
    if (i < n) p[i] = 0;
}

// ---------------- graph normalization ----------------
__global__ void deg_kernel(const int* __restrict__ src, const float* __restrict__ ea) {
    int e = blockIdx.x * blockDim.x + threadIdx.x;
    if (e < EE) atomicAdd(&g_dinv[src[e]], ea[e]);
}

__global__ void dinv_kernel() {
    int i = blockIdx.x * blockDim.x + threadIdx.x;
    if (i < NN) {
        float d = g_dinv[i];
        g_dinv[i] = (d > 0.f) ? rsqrtf(d) : 0.f;
    }
}

__global__ void w_kernel(const int* __restrict__ src, const int* __restrict__ dst,
                         const float* __restrict__ ea) {
    int e = blockIdx.x * blockDim.x + threadIdx.x;
    if (e < EE) g_w[e] = -g_dinv[src[e]] * ea[e] * g_dinv[dst[e]];
}

// ---------------- CSR build ----------------
__global__ void csr_count_kernel(const int* __restrict__ dst) {
    int e = blockIdx.x * blockDim.x + threadIdx.x;
    if (e < EE) atomicAdd(&g_fill[dst[e]], 1);
}

// single-block exclusive scan of g_fill (NN entries) -> g_rowptr, reset g_fill to row start
__global__ void csr_scan_kernel() {
    __shared__ int partial[1024];
    int t = threadIdx.x;
    const int C = CDIV(NN, 1024);
    int lo = t * C;
    int hi = min(lo + C, NN);
    int s = 0;
    for (int i = lo; i < hi; ++i) s += g_fill[i];
    partial[t] = s;
    __syncthreads();
    for (int off = 1; off < 1024; off <<= 1) {
        int v = (t >= off) ? partial[t - off] : 0;
        __syncthreads();
        partial[t] += v;
        __syncthreads();
    }
    int run = (t > 0) ? partial[t - 1] : 0;
    for (int i = lo; i < hi; ++i) {
        int c = g_fill[i];
        g_rowptr[i] = run;
        g_fill[i] = run;
        run += c;
    }
    if (hi == NN && lo <= NN) g_rowptr[NN] = run;
}

__global__ void csr_scatter_kernel(const int* __restrict__ src, const int* __restrict__ dst) {
    int e = blockIdx.x * blockDim.x + threadIdx.x;
    if (e >= EE) return;
    int pos = atomicAdd(&g_fill[dst[e]], 1);
    g_csr_src[pos] = src[e];
    g_csr_w[pos] = g_w[e];
}

// ---------------- weight prep: Wcat[f] = [W0-W2 | W1 | 2*W2] ----------------
__global__ void wprep_kernel(const float* __restrict__ W, float* __restrict__ Wc,
                             int F, int G) {
    int t = blockIdx.x * blockDim.x + threadIdx.x;
    if (t >= F * G) return;
    int f = t / G;
    int c = t - f * G;
    float w0 = W[t];
    float w1 = W[F * G + t];
    float w2 = W[2 * F * G + t];
    Wc[f * 3 * G + c]         = w0 - w2;
    Wc[f * 3 * G + G + c]     = w1;
    Wc[f * 3 * G + 2 * G + c] = 2.f * w2;
}

// ---------------- CSR gather propagate ----------------
// MODE 0: cat.V[n]  = cat.V[n]  + sum_e w * cat.V2[src]          (Z = V + P V2)
// MODE 1: H[n]      = relu(cat.Y0[n] + sum_e w * cat.V[src] + b) (out = relu(Y0 + P Z + b))
// MODE 2: pool[batch[n]] += relu(... same as MODE 1 ...)          (layer-3 fused pooling)
template <int G4, int MODE>
__global__ void gather_kernel(float* __restrict__ cat, float* __restrict__ H,
                              const float* __restrict__ bias,
                              const int* __restrict__ batch) {
    const int ld4 = 3 * G4;
    int tid = blockIdx.x * blockDim.x + threadIdx.x;
    int node = tid / G4;
    int lane = tid % G4;
    if (node >= NN) return;

    const float4* cat4 = (const float4*)cat;
    int beg = g_rowptr[node];
    int end = g_rowptr[node + 1];

    int srcoff = (MODE == 0) ? 2 * G4 : G4;
    float4 acc = cat4[(size_t)node * ld4 + ((MODE == 0) ? G4 : 0) + lane];

    int j = beg;
    for (; j + 1 < end; j += 2) {
        int s0 = g_csr_src[j],     s1 = g_csr_src[j + 1];
        float w0 = g_csr_w[j],     w1 = g_csr_w[j + 1];
        float4 v0 = cat4[(size_t)s0 * ld4 + srcoff + lane];
        float4 v1 = cat4[(size_t)s1 * ld4 + srcoff + lane];
        acc.x = fmaf(w0, v0.x, acc.x); acc.y = fmaf(w0, v0.y, acc.y);
        acc.z = fmaf(w0, v0.z, acc.z); acc.w = fmaf(w0, v0.w, acc.w);
        acc.x = fmaf(w1, v1.x, acc.x); acc.y = fmaf(w1, v1.y, acc.y);
        acc.z = fmaf(w1, v1.z, acc.z); acc.w = fmaf(w1, v1.w, acc.w);
    }
    if (j < end) {
        int s0 = g_csr_src[j];
        float w0 = g_csr_w[j];
        float4 v0 = cat4[(size_t)s0 * ld4 + srcoff + lane];
        acc.x = fmaf(w0, v0.x, acc.x); acc.y = fmaf(w0, v0.y, acc.y);
        acc.z = fmaf(w0, v0.z, acc.z); acc.w = fmaf(w0, v0.w, acc.w);
    }

    if (MODE == 0) {
        ((float4*)cat)[(size_t)node * ld4 + G4 + lane] = acc;
    } else {
        float4 b = ((const float4*)bias)[lane];
        float4 o;
        o.x = fmaxf(acc.x + b.x, 0.f);
        o.y = fmaxf(acc.y + b.y, 0.f);
        o.z = fmaxf(acc.z + b.z, 0.f);
        o.w = fmaxf(acc.w + b.w, 0.f);
        if (MODE == 1) {
            ((float4*)H)[(size_t)node * G4 + lane] = o;
        } else {
            int g = batch[node];
            red_add_v4(&g_pool[g * 32 + lane * 4], o);
        }
    }
}

// ---------------- TF32 tensor-core GEMM (hi/lo 3-term), tiled in N ----------------
template <int BN>
__launch_bounds__(256, 2)
__global__ void gemm_tc_kernel(const float* __restrict__ A,
                               const float* __restrict__ B,
                               float* __restrict__ C,
                               int M, int F, int ldn) {
    const int BM = 128, BK = 16;
    const int WARPS_N = BN / 32;
    const int WARPS_M = 8 / WARPS_N;
    const int WM = BM / WARPS_M;
    const int TM = WM / 16;
    const int TN = 4;

    __shared__ float As_hi[BM][BK + 4];
    __shared__ float As_lo[BM][BK + 4];
    __shared__ float Bs_hi[BK][BN + 4];
    __shared__ float Bs_lo[BK][BN + 4];

    int t = threadIdx.x;
    int warp = t >> 5, lane = t & 31;
    int group = lane >> 2, tg = lane & 3;
    int warp_m = warp % WARPS_M;
    int warp_n = warp / WARPS_M;
    int m_w = warp_m * WM;
    int n_w = warp_n * 32;
    int m0 = blockIdx.x * BM;
    int n0 = blockIdx.y * BN;

    float acc[TM][TN][4];
#pragma unroll
    for (int i = 0; i < TM; ++i)
#pragma unroll
        for (int j = 0; j < TN; ++j)
#pragma unroll
            for (int r = 0; r < 4; ++r) acc[i][j][r] = 0.f;

    for (int k0 = 0; k0 < F; k0 += BK) {
#pragma unroll
        for (int l = 0; l < 2; ++l) {
            int idx = t + l * 256;
            int row = idx >> 2;
            int c4 = (idx & 3) * 4;
            float4 v = make_float4(0.f, 0.f, 0.f, 0.f);
            int m = m0 + row;
            if (m < M) v = *(const float4*)(A + (size_t)m * F + k0 + c4);
            float hx = tf32_hi(v.x), hy = tf32_hi(v.y), hz = tf32_hi(v.z), hw = tf32_hi(v.w);
            *(float4*)&As_hi[row][c4] = make_float4(hx, hy, hz, hw);
            *(float4*)&As_lo[row][c4] = make_float4(tf32_hi(v.x - hx), tf32_hi(v.y - hy),
                                                    tf32_hi(v.z - hz), tf32_hi(v.w - hw));
        }
        for (int idx = t; idx < BK * BN / 4; idx += 256) {
            int row = idx / (BN / 4);
            int c4 = (idx % (BN / 4)) * 4;
            float4 v = *(const float4*)(B + (size_t)(k0 + row) * ldn + n0 + c4);
            float hx = tf32_hi(v.x), hy = tf32_hi(v.y), hz = tf32_hi(v.z), hw = tf32_hi(v.w);
            *(float4*)&Bs_hi[row][c4] = make_float4(hx, hy, hz, hw);
            *(float4*)&Bs_lo[row][c4] = make_float4(tf32_hi(v.x - hx), tf32_hi(v.y - hy),
                                                    tf32_hi(v.z - hz), tf32_hi(v.w - hw));
        }
        __syncthreads();

#pragma unroll
        for (int ks = 0; ks < 2; ++ks) {
            int kb = ks * 8;
            uint32_t bh[TN][2], bl[TN][2];
#pragma unroll
            for (int j = 0; j < TN; ++j) {
                int n = n_w + j * 8 + group;
                bh[j][0] = __float_as_uint(Bs_hi[kb + tg][n]);
                bh[j][1] = __float_as_uint(Bs_hi[kb + tg + 4][n]);
                bl[j][0] = __float_as_uint(Bs_lo[kb + tg][n]);
                bl[j][1] = __float_as_uint(Bs_lo[kb + tg + 4][n]);
            }
#pragma unroll
            for (int i = 0; i < TM; ++i) {
                int mb = m_w + i * 16;
                uint32_t ah[4], al[4];
                ah[0] = __float_as_uint(As_hi[mb + group][kb + tg]);
                ah[1] = __float_as_uint(As_hi[mb + group + 8][kb + tg]);
                ah[2] = __float_as_uint(As_hi[mb + group][kb + tg + 4]);
                ah[3] = __float_as_uint(As_hi[mb + group + 8][kb + tg + 4]);
                al[0] = __float_as_uint(As_lo[mb + group][kb + tg]);
                al[1] = __float_as_uint(As_lo[mb + group + 8][kb + tg]);
                al[2] = __float_as_uint(As_lo[mb + group][kb + tg + 4]);
                al[3] = __float_as_uint(As_lo[mb + group + 8][kb + tg + 4]);
#pragma unroll
                for (int j = 0; j < TN; ++j) {
                    mma_tf32(acc[i][j], ah, bh[j]);
                    mma_tf32(acc[i][j], ah, bl[j]);
                    mma_tf32(acc[i][j], al, bh[j]);
                }
            }
        }
        __syncthreads();
    }

#pragma unroll
    for (int i = 0; i < TM; ++i) {
        int mb = m0 + m_w + i * 16;
        int row0 = mb + group;
        int row1 = mb + group + 8;
#pragma unroll
        for (int j = 0; j < TN; ++j) {
            int n = n0 + n_w + j * 8 + 2 * tg;
            if (row0 < M) {
                C[(size_t)row0 * ldn + n]     = acc[i][j][0];
                C[(size_t)row0 * ldn + n + 1] = acc[i][j][1];
            }
            if (row1 < M) {
                C[(size_t)row1 * ldn + n]     = acc[i][j][2];
                C[(size_t)row1 * ldn + n + 1] = acc[i][j][3];
            }
        }
    }
}

// ---------------- graph node counts + final linear ----------------
__global__ void gcnt_kernel(const int* __restrict__ batch) {
    int i = blockIdx.x * blockDim.x + threadIdx.x;
    if (i < NN) atomicAdd(&g_cnt[batch[i]], 1.0f);
}

__global__ void final_kernel(const float* __restrict__ Wl, const float* __restrict__ bl,
                             float* __restrict__ out) {
    int t = threadIdx.x;
    if (t >= NG * 2) return;
    int g = t >> 1;
    int j = t & 1;
    float cnt = fmaxf(g_cnt[g], 1.0f);
    float s = 0.f;
#pragma unroll
    for (int c = 0; c < 32; ++c) s += g_pool[g * 32 + c] * Wl[c * 2 + j];
    out[t] = s / cnt + bl[j];
}

// ---------------- host orchestration ----------------
extern "C" void kernel_launch(void* const* d_in, const int* in_sizes, int n_in,
                              void* d_out, int out_size) {
    const float* x     = (const float*)d_in[0];
    const int*   ei    = (const int*)d_in[1];
    const float* ea    = (const float*)d_in[2];
    const int*   batch = (const int*)d_in[3];
    const float* W1    = (const float*)d_in[4];
    const float* b1    = (const float*)d_in[5];
    const float* W2    = (const float*)d_in[6];
    const float* b2    = (const float*)d_in[7];
    const float* W3    = (const float*)d_in[8];
    const float* b3    = (const float*)d_in[9];
    const float* Wl    = (const float*)d_in[10];
    const float* bl    = (const float*)d_in[11];
    const int* src = ei;
    const int* dst = ei + EE;

    float *pcat, *pH1, *pH2, *pWc1, *pWc2, *pWc3, *pdinv, *ppool, *pcnt;
    int *pfill;
    cudaGetSymbolAddress((void**)&pcat, g_cat);
    cudaGetSymbolAddress((void**)&pH1,  g_H1);
    cudaGetSymbolAddress((void**)&pH2,  g_H2);
    cudaGetSymbolAddress((void**)&pWc1, g_Wc1);
    cudaGetSymbolAddress((void**)&pWc2, g_Wc2);
    cudaGetSymbolAddress((void**)&pWc3, g_Wc3);
    cudaGetSymbolAddress((void**)&pdinv, g_dinv);
    cudaGetSymbolAddress((void**)&ppool, g_pool);
    cudaGetSymbolAddress((void**)&pcnt,  g_cnt);
    cudaGetSymbolAddress((void**)&pfill, g_fill);

    const int T = 256;

    // normalization weights
    zero_kernel<<<CDIV(NN / 4, T), T>>>((float4*)pdinv, NN / 4);
    deg_kernel<<<CDIV(EE, T), T>>>(src, ea);
    dinv_kernel<<<CDIV(NN, T), T>>>();
    w_kernel<<<CDIV(EE, T), T>>>(src, dst, ea);

    // CSR build (dst-indexed)
    zeroi_kernel<<<CDIV(NN, T), T>>>(pfill, NN);
    csr_count_kernel<<<CDIV(EE, T), T>>>(dst);
    csr_scan_kernel<<<1, 1024>>>();
    csr_scatter_kernel<<<CDIV(EE, T), T>>>(src, dst);

    // concatenated modified weights
    wprep_kernel<<<CDIV(160 * 128, T), T>>>(W1, pWc1, 160, 128);
    wprep_kernel<<<CDIV(128 * 64, T), T>>>(W2, pWc2, 128, 64);
    wprep_kernel<<<CDIV(64 * 32, T), T>>>(W3, pWc3, 64, 32);

    // pool buffers (zeroed early; layer-3 gather red.adds into pool)
    zero_kernel<<<CDIV(NG * 32 / 4, T), T>>>((float4*)ppool, NG * 32 / 4);
    zero_kernel<<<1, T>>>((float4*)pcnt, NG / 4);
    gcnt_kernel<<<CDIV(NN, T), T>>>(batch);

    // ---- layer 1: 160 -> 128 ----
    {
        dim3 grid(CDIV(NN, 128), 3);
        gemm_tc_kernel<128><<<grid, 256>>>(x, pWc1, pcat, NN, 160, 384);
        gather_kernel<32, 0><<<CDIV(NN * 32, T), T>>>(pcat, nullptr, nullptr, nullptr);
        gather_kernel<32, 1><<<CDIV(NN * 32, T), T>>>(pcat, pH1, b1, nullptr);
    }
    // ---- layer 2: 128 -> 64 ----
    {
        dim3 grid(CDIV(NN, 128), 3);
        gemm_tc_kernel<64><<<grid, 256>>>(pH1, pWc2, pcat, NN, 128, 192);
        gather_kernel<16, 0><<<CDIV(NN * 16, T), T>>>(pcat, nullptr, nullptr, nullptr);
        gather_kernel<16, 1><<<CDIV(NN * 16, T), T>>>(pcat, pH2, b2, nullptr);
    }
    // ---- layer 3: 64 -> 32 (pool fused into second gather) ----
    {
        dim3 grid(CDIV(NN, 128), 3);
        gemm_tc_kernel<32><<<grid, 256>>>(pH2, pWc3, pcat, NN, 64, 96);
        gather_kernel<8, 0><<<CDIV(NN * 8, T), T>>>(pcat, nullptr, nullptr, nullptr);
        gather_kernel<8, 2><<<CDIV(NN * 8, T), T>>>(pcat, nullptr, b3, batch);
    }

    final_kernel<<<1, 256>>>(Wl, bl, (float*)d_out);
}